// round 1
// baseline (speedup 1.0000x reference)
#include <cuda_runtime.h>
#include <math.h>

#define NPTS    32768
#define WIDTH   192
#define COND    64
#define KNN     12
#define NLAYERS 4
#define MIXDIM  390
#define MIXPAD  392
#define TPL     32      // points per block (proj / layer)
#define TILE    2048    // knn candidate tile
#define NSPLIT  8       // knn splits per query

// ---- scratch (static device allocations; no cudaMalloc allowed) ----
__device__ float g_h0[NPTS * WIDTH];
__device__ float g_h1[NPTS * WIDTH];
__device__ int   g_knn[NPTS * KNN];
__device__ float g_rel[NPTS * 6];
__device__ float g_zwpb[WIDTH];
__device__ float g_gamma[NLAYERS * WIDTH];
__device__ float g_beta[NLAYERS * WIDTH];

// ============================================================
// Setup: z-dependent constants (proj bias, FiLM gamma/beta)
// ============================================================
__global__ void setup_kernel(const float* __restrict__ z,
                             const float* __restrict__ Wp, const float* __restrict__ bp,
                             const float* __restrict__ Wg, const float* __restrict__ bg,
                             const float* __restrict__ Wb, const float* __restrict__ bb) {
    int c = threadIdx.x;
    if (c >= WIDTH) return;
    float s = bp[c];
    for (int k = 0; k < COND; k++)
        s = fmaf(z[k], Wp[(51 + k) * WIDTH + c], s);
    g_zwpb[c] = s;
    for (int li = 0; li < NLAYERS; li++) {
        const float* wg = Wg + li * COND * WIDTH;
        const float* wb = Wb + li * COND * WIDTH;
        float g = bg[li * WIDTH + c];
        float b = bb[li * WIDTH + c];
        for (int k = 0; k < COND; k++) {
            float zk = z[k];
            g = fmaf(zk, wg[k * WIDTH + c], g);
            b = fmaf(zk, wb[k * WIDTH + c], b);
        }
        g_gamma[li * WIDTH + c] = g;
        g_beta[li * WIDTH + c]  = b;
    }
}

// ============================================================
// kNN: 32 queries/block, 8 candidate-splits per query.
// Warp = 32 queries scanning the SAME candidate (broadcast LDS).
// Per-split sorted top-12 in registers; merge in shared.
// Also emits rel_feat (mean/std of relative coords).
// ============================================================
__global__ __launch_bounds__(256) void knn_kernel(const float* __restrict__ x, int n) {
    __shared__ float4 tile[TILE];                 // 32 KB, aliased for merge after use
    __shared__ int    sel[32][KNN];
    float* md = (float*)tile;                     // [32][97] padded (bank-conflict free)
    int*   mi = (int*)(md + 32 * 97);             // [32][97]

    int tx = threadIdx.x;           // query lane 0..31
    int ty = threadIdx.y;           // split 0..7
    int qi = blockIdx.x * 32 + tx;

    float qx = x[qi * 3 + 0];
    float qy = x[qi * 3 + 1];
    float qz = x[qi * 3 + 2];

    float bd[KNN];
    int   bi[KNN];
#pragma unroll
    for (int s = 0; s < KNN; s++) { bd[s] = 1e30f; bi[s] = -1; }
    float bd11 = 1e30f;

    int lin = ty * 32 + tx;
    for (int tb = 0; tb < n; tb += TILE) {
        __syncthreads();
        for (int i = lin; i < TILE; i += 256) {
            int j = tb + i;
            tile[i] = make_float4(x[j * 3 + 0], x[j * 3 + 1], x[j * 3 + 2], 0.0f);
        }
        __syncthreads();
#pragma unroll 4
        for (int t = 0; t < TILE / NSPLIT; t++) {
            int jl = t * NSPLIT + ty;
            float4 cf = tile[jl];
            float dx = cf.x - qx, dy = cf.y - qy, dz = cf.z - qz;
            float d  = fmaf(dx, dx, fmaf(dy, dy, dz * dz));
            int gj = tb + jl;
            if (d < bd11 && gj != qi) {
                float cd = d; int ci = gj;
#pragma unroll
                for (int s = 0; s < KNN; s++) {
                    bool lt = cd < bd[s];
                    float od = bd[s]; int oi = bi[s];
                    bd[s] = lt ? cd : od;  bi[s] = lt ? ci : oi;
                    cd    = lt ? od : cd;  ci    = lt ? oi : ci;
                }
                bd11 = bd[KNN - 1];
            }
        }
    }
    __syncthreads();   // tile reads done; safe to alias
#pragma unroll
    for (int r = 0; r < KNN; r++) {
        md[tx * 97 + ty * KNN + r] = bd[r];
        mi[tx * 97 + ty * KNN + r] = bi[r];
    }
    __syncthreads();

    if (ty == 0) {
        // merge: pick 12 smallest of 96 (destructive selection)
        for (int r = 0; r < KNN; r++) {
            float best = 1e30f; int bs = 0;
            for (int s = 0; s < NSPLIT * KNN; s++) {
                float v = md[tx * 97 + s];
                if (v < best) { best = v; bs = s; }
            }
            int id = mi[tx * 97 + bs];
            md[tx * 97 + bs] = 1e31f;
            g_knn[qi * KNN + r] = id;
            sel[tx][r] = id;
        }
        // rel_feat: mean + population std of (x[nbr] - x[q])
        float mx = 0, my = 0, mz = 0;
#pragma unroll
        for (int r = 0; r < KNN; r++) {
            int id = sel[tx][r];
            mx += x[id * 3 + 0] - qx;
            my += x[id * 3 + 1] - qy;
            mz += x[id * 3 + 2] - qz;
        }
        const float inv = 1.0f / (float)KNN;
        mx *= inv; my *= inv; mz *= inv;
        float vx = 0, vy = 0, vz = 0;
#pragma unroll
        for (int r = 0; r < KNN; r++) {
            int id = sel[tx][r];
            float rx = x[id * 3 + 0] - qx - mx;
            float ry = x[id * 3 + 1] - qy - my;
            float rz = x[id * 3 + 2] - qz - mz;
            vx = fmaf(rx, rx, vx); vy = fmaf(ry, ry, vy); vz = fmaf(rz, rz, vz);
        }
        g_rel[qi * 6 + 0] = mx;
        g_rel[qi * 6 + 1] = my;
        g_rel[qi * 6 + 2] = mz;
        g_rel[qi * 6 + 3] = sqrtf(vx * inv);
        g_rel[qi * 6 + 4] = sqrtf(vy * inv);
        g_rel[qi * 6 + 5] = sqrtf(vz * inv);
    }
}

// ============================================================
// Projection: pe = fourier(x) (51 dims), h0 = silu(pe@Wp[0:51] + zwpb)
// ============================================================
__global__ __launch_bounds__(192) void proj_kernel(const float* __restrict__ x,
                                                   const float* __restrict__ B0,
                                                   const float* __restrict__ B1,
                                                   const float* __restrict__ B2,
                                                   const float* __restrict__ Wp,
                                                   float* __restrict__ hout) {
    __shared__ float pe[TPL][52];
    int c    = threadIdx.x;
    int base = blockIdx.x * TPL;

    if (c < TPL) {
        int p = base + c;
        float x0 = x[p * 3 + 0], x1 = x[p * 3 + 1], x2 = x[p * 3 + 2];
        const float* Bs[3] = { B0, B1, B2 };
#pragma unroll
        for (int b = 0; b < 3; b++) {
            const float* B = Bs[b];
#pragma unroll
            for (int j = 0; j < 8; j++) {
                float v = fmaf(x0, B[j], fmaf(x1, B[8 + j], x2 * B[16 + j]));
                float sn, cs;
                sincosf(v, &sn, &cs);
                pe[c][b * 16 + j]     = sn;
                pe[c][b * 16 + 8 + j] = cs;
            }
        }
        pe[c][48] = x0; pe[c][49] = x1; pe[c][50] = x2;
    }
    __syncthreads();

    float acc[TPL];
    float zb = g_zwpb[c];
#pragma unroll
    for (int p = 0; p < TPL; p++) acc[p] = zb;
    for (int k = 0; k < 51; k++) {
        float w = Wp[k * WIDTH + c];
#pragma unroll
        for (int p = 0; p < TPL; p++)
            acc[p] = fmaf(pe[p][k], w, acc[p]);
    }
#pragma unroll
    for (int p = 0; p < TPL; p++) {
        float v = acc[p];
        hout[(base + p) * WIDTH + c] = v / (1.0f + expf(-v));
    }
}

// ============================================================
// Layer: gather+mean agg, mix=[h|agg|rel] in shared, 390x192 GEMM,
// silu + FiLM. One thread = one output column, 32 points/block.
// ============================================================
__global__ __launch_bounds__(192) void layer_kernel(const float* __restrict__ hin,
                                                    float* __restrict__ hout,
                                                    const float* __restrict__ Wl,
                                                    const float* __restrict__ bl,
                                                    const float* __restrict__ gamma,
                                                    const float* __restrict__ beta) {
    extern __shared__ float mix[];       // [TPL][MIXPAD]
    __shared__ int nidx[TPL * KNN];
    int c    = threadIdx.x;
    int base = blockIdx.x * TPL;

    for (int i = c; i < TPL * KNN; i += 192)
        nidx[i] = g_knn[base * KNN + i];
    __syncthreads();

#pragma unroll
    for (int p = 0; p < TPL; p++)
        mix[p * MIXPAD + c] = hin[(base + p) * WIDTH + c];
    if (c < 6) {
        for (int p = 0; p < TPL; p++)
            mix[p * MIXPAD + 384 + c] = g_rel[(base + p) * 6 + c];
    }
    for (int p = 0; p < TPL; p++) {
        float s = 0.0f;
#pragma unroll
        for (int j = 0; j < KNN; j++)
            s += hin[nidx[p * KNN + j] * WIDTH + c];
        mix[p * MIXPAD + WIDTH + c] = s * (1.0f / (float)KNN);
    }
    __syncthreads();

    float acc[TPL];
#pragma unroll
    for (int p = 0; p < TPL; p++) acc[p] = 0.0f;

    for (int k4 = 0; k4 < 97; k4++) {
        int k = k4 * 4;
        float w0 = Wl[(k + 0) * WIDTH + c];
        float w1 = Wl[(k + 1) * WIDTH + c];
        float w2 = Wl[(k + 2) * WIDTH + c];
        float w3 = Wl[(k + 3) * WIDTH + c];
#pragma unroll
        for (int p = 0; p < TPL; p++) {
            float4 m = *reinterpret_cast<const float4*>(&mix[p * MIXPAD + k]);
            acc[p] = fmaf(m.x, w0, acc[p]);
            acc[p] = fmaf(m.y, w1, acc[p]);
            acc[p] = fmaf(m.z, w2, acc[p]);
            acc[p] = fmaf(m.w, w3, acc[p]);
        }
    }
    {   // tail k = 388, 389
        float w0 = Wl[388 * WIDTH + c];
        float w1 = Wl[389 * WIDTH + c];
#pragma unroll
        for (int p = 0; p < TPL; p++) {
            acc[p] = fmaf(mix[p * MIXPAD + 388], w0, acc[p]);
            acc[p] = fmaf(mix[p * MIXPAD + 389], w1, acc[p]);
        }
    }

    float bc = bl[c], gc = gamma[c], bt = beta[c];
#pragma unroll
    for (int p = 0; p < TPL; p++) {
        float v  = acc[p] + bc;
        float sv = v / (1.0f + expf(-v));
        hout[(base + p) * WIDTH + c] = fmaf(sv, gc, bt);
    }
}

// ============================================================
// Output: out = (h @ Wout + bout) * 0.01 ; one warp per point
// ============================================================
__global__ __launch_bounds__(256) void out_kernel(const float* __restrict__ h,
                                                  const float* __restrict__ Wout,
                                                  const float* __restrict__ bout,
                                                  float* __restrict__ out, int n) {
    int gwarp = (blockIdx.x * blockDim.x + threadIdx.x) >> 5;
    int lane  = threadIdx.x & 31;
    if (gwarp >= n) return;
    float o0 = 0, o1 = 0, o2 = 0;
    for (int c = lane; c < WIDTH; c += 32) {
        float hv = h[gwarp * WIDTH + c];
        o0 = fmaf(hv, Wout[c * 3 + 0], o0);
        o1 = fmaf(hv, Wout[c * 3 + 1], o1);
        o2 = fmaf(hv, Wout[c * 3 + 2], o2);
    }
#pragma unroll
    for (int off = 16; off; off >>= 1) {
        o0 += __shfl_down_sync(0xffffffffu, o0, off);
        o1 += __shfl_down_sync(0xffffffffu, o1, off);
        o2 += __shfl_down_sync(0xffffffffu, o2, off);
    }
    if (lane == 0) {
        out[gwarp * 3 + 0] = (o0 + bout[0]) * 0.01f;
        out[gwarp * 3 + 1] = (o1 + bout[1]) * 0.01f;
        out[gwarp * 3 + 2] = (o2 + bout[2]) * 0.01f;
    }
}

// ============================================================
extern "C" void kernel_launch(void* const* d_in, const int* in_sizes, int n_in,
                              void* d_out, int out_size) {
    const float* x    = (const float*)d_in[0];
    const float* z    = (const float*)d_in[1];
    const float* B0   = (const float*)d_in[2];
    const float* B1   = (const float*)d_in[3];
    const float* B2   = (const float*)d_in[4];
    const float* Wp   = (const float*)d_in[5];
    const float* bp   = (const float*)d_in[6];
    const float* Wl   = (const float*)d_in[7];
    const float* bl   = (const float*)d_in[8];
    const float* Wg   = (const float*)d_in[9];
    const float* bg   = (const float*)d_in[10];
    const float* Wb   = (const float*)d_in[11];
    const float* Wbb  = (const float*)d_in[12];
    const float* Wout = (const float*)d_in[13];
    const float* bout = (const float*)d_in[14];
    float* out = (float*)d_out;

    int n = in_sizes[0] / 3;   // 32768

    float *h0, *h1;
    cudaGetSymbolAddress((void**)&h0, g_h0);
    cudaGetSymbolAddress((void**)&h1, g_h1);
    float *gma, *bta;
    cudaGetSymbolAddress((void**)&gma, g_gamma);
    cudaGetSymbolAddress((void**)&bta, g_beta);

    const int smem_layer = TPL * MIXPAD * (int)sizeof(float);  // 50176
    cudaFuncSetAttribute(layer_kernel, cudaFuncAttributeMaxDynamicSharedMemorySize, smem_layer);

    setup_kernel<<<1, WIDTH>>>(z, Wp, bp, Wg, bg, Wb, Wbb);
    knn_kernel<<<n / 32, dim3(32, NSPLIT)>>>(x, n);
    proj_kernel<<<n / TPL, WIDTH>>>(x, B0, B1, B2, Wp, h0);

    float* bufs[2] = { h0, h1 };
    for (int li = 0; li < NLAYERS; li++) {
        const float* hin = bufs[li & 1];
        float*       ho  = bufs[(li + 1) & 1];
        layer_kernel<<<n / TPL, WIDTH, smem_layer>>>(hin, ho,
            Wl + (size_t)li * MIXDIM * WIDTH, bl + li * WIDTH,
            gma + li * WIDTH, bta + li * WIDTH);
    }
    const float* hfin = bufs[NLAYERS & 1];

    out_kernel<<<(n * 32 + 255) / 256, 256>>>(hfin, Wout, bout, out, n);
}

// round 2
// speedup vs baseline: 1.1333x; 1.1333x over previous
#include <cuda_runtime.h>
#include <math.h>

#define NPTS    32768
#define WIDTH   192
#define COND    64
#define KNN     12
#define NLAYERS 4
#define MIXDIM  390
#define MIXPAD  392
#define TPL     32      // points per block (proj / layer)

// ---- spatial grid for kNN ----
#define G       64
#define NCELLS  (G*G*G)          // 262144
#define GLO     (-6.0f)
#define GH      (0.1875f)        // 12/64
#define INVH    (1.0f/0.1875f)

// ---- scratch (static device allocations; no cudaMalloc allowed) ----
__device__ float  g_h0[NPTS * WIDTH];
__device__ float  g_h1[NPTS * WIDTH];
__device__ int    g_knn[NPTS * KNN];
__device__ float  g_rel[NPTS * 6];
__device__ float  g_zwpb[WIDTH];
__device__ float  g_gamma[NLAYERS * WIDTH];
__device__ float  g_beta[NLAYERS * WIDTH];

__device__ int    g_cnt[NCELLS];
__device__ int    g_start[NCELLS];
__device__ int    g_cursor[NCELLS];
__device__ int    g_partial[NCELLS / 1024];   // 256
__device__ float4 g_pts[NPTS];                // sorted (x,y,z, orig-idx-as-bits)

__device__ __forceinline__ int cell_coord(float v) {
    int c = (int)((v - GLO) * INVH);
    return min(G - 1, max(0, c));
}

// ============================================================
// Setup: z-dependent constants (proj bias, FiLM gamma/beta)
// ============================================================
__global__ void setup_kernel(const float* __restrict__ z,
                             const float* __restrict__ Wp, const float* __restrict__ bp,
                             const float* __restrict__ Wg, const float* __restrict__ bg,
                             const float* __restrict__ Wb, const float* __restrict__ bb) {
    int c = threadIdx.x;
    if (c >= WIDTH) return;
    float s = bp[c];
    for (int k = 0; k < COND; k++)
        s = fmaf(z[k], Wp[(51 + k) * WIDTH + c], s);
    g_zwpb[c] = s;
    for (int li = 0; li < NLAYERS; li++) {
        const float* wg = Wg + li * COND * WIDTH;
        const float* wb = Wb + li * COND * WIDTH;
        float g = bg[li * WIDTH + c];
        float b = bb[li * WIDTH + c];
        for (int k = 0; k < COND; k++) {
            float zk = z[k];
            g = fmaf(zk, wg[k * WIDTH + c], g);
            b = fmaf(zk, wb[k * WIDTH + c], b);
        }
        g_gamma[li * WIDTH + c] = g;
        g_beta[li * WIDTH + c]  = b;
    }
}

// ============================================================
// Grid build: histogram -> 2-level exclusive scan -> scatter
// ============================================================
__global__ void hist_kernel(const float* __restrict__ x, int n) {
    int i = blockIdx.x * blockDim.x + threadIdx.x;
    if (i >= n) return;
    int cx = cell_coord(x[i * 3 + 0]);
    int cy = cell_coord(x[i * 3 + 1]);
    int cz = cell_coord(x[i * 3 + 2]);
    atomicAdd(&g_cnt[(cz * G + cy) * G + cx], 1);
}

__global__ void scan1_kernel() {
    __shared__ int sh[1024];
    int gid = blockIdx.x * 1024 + threadIdx.x;
    int v = g_cnt[gid];
    sh[threadIdx.x] = v;
    __syncthreads();
    for (int off = 1; off < 1024; off <<= 1) {
        int t = (threadIdx.x >= off) ? sh[threadIdx.x - off] : 0;
        __syncthreads();
        sh[threadIdx.x] += t;
        __syncthreads();
    }
    g_start[gid] = sh[threadIdx.x] - v;          // exclusive within block
    if (threadIdx.x == 1023) g_partial[blockIdx.x] = sh[1023];
}

__global__ void scan2_kernel() {
    __shared__ int sh[256];
    int v = g_partial[threadIdx.x];
    sh[threadIdx.x] = v;
    __syncthreads();
    for (int off = 1; off < 256; off <<= 1) {
        int t = (threadIdx.x >= off) ? sh[threadIdx.x - off] : 0;
        __syncthreads();
        sh[threadIdx.x] += t;
        __syncthreads();
    }
    g_partial[threadIdx.x] = sh[threadIdx.x] - v;  // exclusive block offsets
}

__global__ void scan3_kernel() {
    int gid = blockIdx.x * 1024 + threadIdx.x;
    int s = g_start[gid] + g_partial[blockIdx.x];
    g_start[gid]  = s;
    g_cursor[gid] = s;
}

__global__ void scatter_kernel(const float* __restrict__ x, int n) {
    int i = blockIdx.x * blockDim.x + threadIdx.x;
    if (i >= n) return;
    float px = x[i * 3 + 0], py = x[i * 3 + 1], pz = x[i * 3 + 2];
    int cx = cell_coord(px), cy = cell_coord(py), cz = cell_coord(pz);
    int cell = (cz * G + cy) * G + cx;
    int slot = atomicAdd(&g_cursor[cell], 1);
    g_pts[slot] = make_float4(px, py, pz, __int_as_float(i));
}

// ============================================================
// kNN query: one thread per (sorted) point; expanding Chebyshev
// rings with AABB pruning; exact stop: d12 <= (r*h)^2.
// Also emits rel_feat (mean/std of relative coords).
// ============================================================
__global__ __launch_bounds__(256) void knn_query_kernel(const float* __restrict__ x, int n) {
    int s = blockIdx.x * blockDim.x + threadIdx.x;
    if (s >= n) return;
    float4 me = g_pts[s];
    float qx = me.x, qy = me.y, qz = me.z;
    int   qi = __float_as_int(me.w);
    int cx = cell_coord(qx), cy = cell_coord(qy), cz = cell_coord(qz);

    float bd[KNN];
    int   bi[KNN];
#pragma unroll
    for (int r = 0; r < KNN; r++) { bd[r] = 1e30f; bi[r] = -1; }
    float d12 = 1e30f;

    for (int r = 0; r < G; r++) {
        for (int dz = -r; dz <= r; dz++) {
            int ccz = cz + dz;
            if (ccz < 0 || ccz >= G) continue;
            bool zface = (dz == -r) || (dz == r);
            for (int dy = -r; dy <= r; dy++) {
                int ccy = cy + dy;
                if (ccy < 0 || ccy >= G) continue;
                bool face = zface || (dy == -r) || (dy == r);
                int step = face ? 1 : (2 * r);     // interior rows: only dx = +-r
                for (int dx = -r; dx <= r; dx += step) {
                    int ccx = cx + dx;
                    if (ccx < 0 || ccx >= G) continue;
                    int cell = (ccz * G + ccy) * G + ccx;
                    int cnt = g_cnt[cell];
                    if (cnt == 0) continue;
                    // AABB min-dist prune
                    float lox = GLO + ccx * GH;
                    float loy = GLO + ccy * GH;
                    float loz = GLO + ccz * GH;
                    float ax = fmaxf(fmaxf(lox - qx, qx - (lox + GH)), 0.0f);
                    float ay = fmaxf(fmaxf(loy - qy, qy - (loy + GH)), 0.0f);
                    float az = fmaxf(fmaxf(loz - qz, qz - (loz + GH)), 0.0f);
                    float dmin = fmaf(ax, ax, fmaf(ay, ay, az * az));
                    if (dmin >= d12) continue;
                    int st = g_start[cell];
                    for (int j = st; j < st + cnt; j++) {
                        float4 p = g_pts[j];
                        float ddx = p.x - qx, ddy = p.y - qy, ddz = p.z - qz;
                        float d = fmaf(ddx, ddx, fmaf(ddy, ddy, ddz * ddz));
                        int pid = __float_as_int(p.w);
                        if (d < d12 && pid != qi) {
                            float cd = d; int ci = pid;
#pragma unroll
                            for (int t = 0; t < KNN; t++) {
                                bool lt = cd < bd[t];
                                float od = bd[t]; int oi = bi[t];
                                bd[t] = lt ? cd : od;  bi[t] = lt ? ci : oi;
                                cd    = lt ? od : cd;  ci    = lt ? oi : ci;
                            }
                            d12 = bd[KNN - 1];
                        }
                    }
                }
            }
        }
        float rb = (float)r * GH;
        if (d12 <= rb * rb) break;      // all unsearched cells are >= r*h away
    }

#pragma unroll
    for (int r = 0; r < KNN; r++)
        g_knn[qi * KNN + r] = bi[r];

    // rel_feat: mean + population std of (x[nbr] - x[q])
    float mx = 0, my = 0, mz = 0;
#pragma unroll
    for (int r = 0; r < KNN; r++) {
        int id = bi[r];
        mx += x[id * 3 + 0] - qx;
        my += x[id * 3 + 1] - qy;
        mz += x[id * 3 + 2] - qz;
    }
    const float inv = 1.0f / (float)KNN;
    mx *= inv; my *= inv; mz *= inv;
    float vx = 0, vy = 0, vz = 0;
#pragma unroll
    for (int r = 0; r < KNN; r++) {
        int id = bi[r];
        float rx = x[id * 3 + 0] - qx - mx;
        float ry = x[id * 3 + 1] - qy - my;
        float rz = x[id * 3 + 2] - qz - mz;
        vx = fmaf(rx, rx, vx); vy = fmaf(ry, ry, vy); vz = fmaf(rz, rz, vz);
    }
    g_rel[qi * 6 + 0] = mx;
    g_rel[qi * 6 + 1] = my;
    g_rel[qi * 6 + 2] = mz;
    g_rel[qi * 6 + 3] = sqrtf(vx * inv);
    g_rel[qi * 6 + 4] = sqrtf(vy * inv);
    g_rel[qi * 6 + 5] = sqrtf(vz * inv);
}

// ============================================================
// Projection: pe = fourier(x) (51 dims), h0 = silu(pe@Wp[0:51] + zwpb)
// ============================================================
__global__ __launch_bounds__(192) void proj_kernel(const float* __restrict__ x,
                                                   const float* __restrict__ B0,
                                                   const float* __restrict__ B1,
                                                   const float* __restrict__ B2,
                                                   const float* __restrict__ Wp,
                                                   float* __restrict__ hout) {
    __shared__ float pe[TPL][52];
    int c    = threadIdx.x;
    int base = blockIdx.x * TPL;

    if (c < TPL) {
        int p = base + c;
        float x0 = x[p * 3 + 0], x1 = x[p * 3 + 1], x2 = x[p * 3 + 2];
        const float* Bs[3] = { B0, B1, B2 };
#pragma unroll
        for (int b = 0; b < 3; b++) {
            const float* B = Bs[b];
#pragma unroll
            for (int j = 0; j < 8; j++) {
                float v = fmaf(x0, B[j], fmaf(x1, B[8 + j], x2 * B[16 + j]));
                float sn, cs;
                sincosf(v, &sn, &cs);
                pe[c][b * 16 + j]     = sn;
                pe[c][b * 16 + 8 + j] = cs;
            }
        }
        pe[c][48] = x0; pe[c][49] = x1; pe[c][50] = x2;
    }
    __syncthreads();

    float acc[TPL];
    float zb = g_zwpb[c];
#pragma unroll
    for (int p = 0; p < TPL; p++) acc[p] = zb;
    for (int k = 0; k < 51; k++) {
        float w = Wp[k * WIDTH + c];
#pragma unroll
        for (int p = 0; p < TPL; p++)
            acc[p] = fmaf(pe[p][k], w, acc[p]);
    }
#pragma unroll
    for (int p = 0; p < TPL; p++) {
        float v = acc[p];
        hout[(base + p) * WIDTH + c] = v / (1.0f + expf(-v));
    }
}

// ============================================================
// Layer: gather+mean agg, mix=[h|agg|rel] in shared, 390x192 GEMM,
// silu + FiLM. One thread = one output column, 32 points/block.
// ============================================================
__global__ __launch_bounds__(192) void layer_kernel(const float* __restrict__ hin,
                                                    float* __restrict__ hout,
                                                    const float* __restrict__ Wl,
                                                    const float* __restrict__ bl,
                                                    const float* __restrict__ gamma,
                                                    const float* __restrict__ beta) {
    extern __shared__ float mix[];       // [TPL][MIXPAD]
    __shared__ int nidx[TPL * KNN];
    int c    = threadIdx.x;
    int base = blockIdx.x * TPL;

    for (int i = c; i < TPL * KNN; i += 192)
        nidx[i] = g_knn[base * KNN + i];
    __syncthreads();

#pragma unroll
    for (int p = 0; p < TPL; p++)
        mix[p * MIXPAD + c] = hin[(base + p) * WIDTH + c];
    if (c < 6) {
        for (int p = 0; p < TPL; p++)
            mix[p * MIXPAD + 384 + c] = g_rel[(base + p) * 6 + c];
    }
    for (int p = 0; p < TPL; p++) {
        float s = 0.0f;
#pragma unroll
        for (int j = 0; j < KNN; j++)
            s += hin[nidx[p * KNN + j] * WIDTH + c];
        mix[p * MIXPAD + WIDTH + c] = s * (1.0f / (float)KNN);
    }
    __syncthreads();

    float acc[TPL];
#pragma unroll
    for (int p = 0; p < TPL; p++) acc[p] = 0.0f;

    for (int k4 = 0; k4 < 97; k4++) {
        int k = k4 * 4;
        float w0 = Wl[(k + 0) * WIDTH + c];
        float w1 = Wl[(k + 1) * WIDTH + c];
        float w2 = Wl[(k + 2) * WIDTH + c];
        float w3 = Wl[(k + 3) * WIDTH + c];
#pragma unroll
        for (int p = 0; p < TPL; p++) {
            float4 m = *reinterpret_cast<const float4*>(&mix[p * MIXPAD + k]);
            acc[p] = fmaf(m.x, w0, acc[p]);
            acc[p] = fmaf(m.y, w1, acc[p]);
            acc[p] = fmaf(m.z, w2, acc[p]);
            acc[p] = fmaf(m.w, w3, acc[p]);
        }
    }
    {   // tail k = 388, 389
        float w0 = Wl[388 * WIDTH + c];
        float w1 = Wl[389 * WIDTH + c];
#pragma unroll
        for (int p = 0; p < TPL; p++) {
            acc[p] = fmaf(mix[p * MIXPAD + 388], w0, acc[p]);
            acc[p] = fmaf(mix[p * MIXPAD + 389], w1, acc[p]);
        }
    }

    float bc = bl[c], gc = gamma[c], bt = beta[c];
#pragma unroll
    for (int p = 0; p < TPL; p++) {
        float v  = acc[p] + bc;
        float sv = v / (1.0f + expf(-v));
        hout[(base + p) * WIDTH + c] = fmaf(sv, gc, bt);
    }
}

// ============================================================
// Output: out = (h @ Wout + bout) * 0.01 ; one warp per point
// ============================================================
__global__ __launch_bounds__(256) void out_kernel(const float* __restrict__ h,
                                                  const float* __restrict__ Wout,
                                                  const float* __restrict__ bout,
                                                  float* __restrict__ out, int n) {
    int gwarp = (blockIdx.x * blockDim.x + threadIdx.x) >> 5;
    int lane  = threadIdx.x & 31;
    if (gwarp >= n) return;
    float o0 = 0, o1 = 0, o2 = 0;
    for (int c = lane; c < WIDTH; c += 32) {
        float hv = h[gwarp * WIDTH + c];
        o0 = fmaf(hv, Wout[c * 3 + 0], o0);
        o1 = fmaf(hv, Wout[c * 3 + 1], o1);
        o2 = fmaf(hv, Wout[c * 3 + 2], o2);
    }
#pragma unroll
    for (int off = 16; off; off >>= 1) {
        o0 += __shfl_down_sync(0xffffffffu, o0, off);
        o1 += __shfl_down_sync(0xffffffffu, o1, off);
        o2 += __shfl_down_sync(0xffffffffu, o2, off);
    }
    if (lane == 0) {
        out[gwarp * 3 + 0] = (o0 + bout[0]) * 0.01f;
        out[gwarp * 3 + 1] = (o1 + bout[1]) * 0.01f;
        out[gwarp * 3 + 2] = (o2 + bout[2]) * 0.01f;
    }
}

// ============================================================
extern "C" void kernel_launch(void* const* d_in, const int* in_sizes, int n_in,
                              void* d_out, int out_size) {
    const float* x    = (const float*)d_in[0];
    const float* z    = (const float*)d_in[1];
    const float* B0   = (const float*)d_in[2];
    const float* B1   = (const float*)d_in[3];
    const float* B2   = (const float*)d_in[4];
    const float* Wp   = (const float*)d_in[5];
    const float* bp   = (const float*)d_in[6];
    const float* Wl   = (const float*)d_in[7];
    const float* bl   = (const float*)d_in[8];
    const float* Wg   = (const float*)d_in[9];
    const float* bg   = (const float*)d_in[10];
    const float* Wb   = (const float*)d_in[11];
    const float* Wbb  = (const float*)d_in[12];
    const float* Wout = (const float*)d_in[13];
    const float* bout = (const float*)d_in[14];
    float* out = (float*)d_out;

    int n = in_sizes[0] / 3;   // 32768

    float *h0, *h1;
    cudaGetSymbolAddress((void**)&h0, g_h0);
    cudaGetSymbolAddress((void**)&h1, g_h1);
    float *gma, *bta;
    cudaGetSymbolAddress((void**)&gma, g_gamma);
    cudaGetSymbolAddress((void**)&bta, g_beta);
    void* cntp;
    cudaGetSymbolAddress(&cntp, g_cnt);

    const int smem_layer = TPL * MIXPAD * (int)sizeof(float);  // 50176
    cudaFuncSetAttribute(layer_kernel, cudaFuncAttributeMaxDynamicSharedMemorySize, smem_layer);

    setup_kernel<<<1, WIDTH>>>(z, Wp, bp, Wg, bg, Wb, Wbb);

    // ---- grid kNN pipeline ----
    cudaMemsetAsync(cntp, 0, NCELLS * sizeof(int));
    hist_kernel<<<n / 256, 256>>>(x, n);
    scan1_kernel<<<NCELLS / 1024, 1024>>>();
    scan2_kernel<<<1, 256>>>();
    scan3_kernel<<<NCELLS / 1024, 1024>>>();
    scatter_kernel<<<n / 256, 256>>>(x, n);
    knn_query_kernel<<<n / 256, 256>>>(x, n);

    proj_kernel<<<n / TPL, WIDTH>>>(x, B0, B1, B2, Wp, h0);

    float* bufs[2] = { h0, h1 };
    for (int li = 0; li < NLAYERS; li++) {
        const float* hin = bufs[li & 1];
        float*       ho  = bufs[(li + 1) & 1];
        layer_kernel<<<n / TPL, WIDTH, smem_layer>>>(hin, ho,
            Wl + (size_t)li * MIXDIM * WIDTH, bl + li * WIDTH,
            gma + li * WIDTH, bta + li * WIDTH);
    }
    const float* hfin = bufs[NLAYERS & 1];

    out_kernel<<<(n * 32 + 255) / 256, 256>>>(hfin, Wout, bout, out, n);
}

// round 3
// speedup vs baseline: 1.7679x; 1.5599x over previous
#include <cuda_runtime.h>
#include <math.h>

#define NPTS    32768
#define WIDTH   192
#define COND    64
#define KNN     12
#define NLAYERS 4
#define MIXDIM  390
#define MIXPAD  392
#define TPL     32      // points per block (proj)
#define TPL2    16      // points per block (layer)

// ---- quantile grid for kNN ----
#define G       16
#define NCELLS  (G*G*G)          // 4096

typedef unsigned long long ull;

// ---- scratch (static device allocations; no cudaMalloc allowed) ----
__device__ float  g_h0[NPTS * WIDTH];
__device__ float  g_h1[NPTS * WIDTH];
__device__ int    g_knn[NPTS * KNN];
__device__ float  g_rel[NPTS * 6];
__device__ float  g_zwpb[WIDTH];
__device__ float  g_gamma[NLAYERS * WIDTH];
__device__ float  g_beta[NLAYERS * WIDTH];

__device__ float  g_bx[G + 1];        // quantile boundaries in x-space
__device__ int    g_cnt[NCELLS];
__device__ int    g_cursor[NCELLS];
__device__ int2   g_cell2[NCELLS];    // (start, end)
__device__ float4 g_pts[NPTS];        // sorted (x,y,z, orig-idx-as-bits)

// ---- packed f32x2 helpers (FFMA2) ----
__device__ __forceinline__ ull pk2(float a, float b) {
    ull r; asm("mov.b64 %0,{%1,%2};" : "=l"(r) : "f"(a), "f"(b)); return r;
}
__device__ __forceinline__ ull fma2(ull a, ull b, ull c) {
    ull d; asm("fma.rn.f32x2 %0,%1,%2,%3;" : "=l"(d) : "l"(a), "l"(b), "l"(c)); return d;
}
__device__ __forceinline__ void upk2(ull v, float& a, float& b) {
    asm("mov.b64 {%0,%1},%2;" : "=f"(a), "=f"(b) : "l"(v));
}

__device__ __forceinline__ int cell_of(float v, const float* bx) {
    int lo = 0;
    if (v >= bx[8])      lo = 8;
    if (v >= bx[lo + 4]) lo += 4;
    if (v >= bx[lo + 2]) lo += 2;
    if (v >= bx[lo + 1]) lo += 1;
    return lo;           // bx[lo] <= v < bx[lo+1]
}

// ============================================================
// Setup: z-dependent constants + quantile boundaries
// ============================================================
__global__ void setup_kernel(const float* __restrict__ z,
                             const float* __restrict__ Wp, const float* __restrict__ bp,
                             const float* __restrict__ Wg, const float* __restrict__ bg,
                             const float* __restrict__ Wb, const float* __restrict__ bb) {
    int c = threadIdx.x;
    if (c <= G) {
        g_bx[c] = (c == 0) ? -1e9f : ((c == G) ? 1e9f
                  : normcdfinvf((float)c / (float)G));
    }
    if (c >= WIDTH) return;
    float s = bp[c];
    for (int k = 0; k < COND; k++)
        s = fmaf(z[k], Wp[(51 + k) * WIDTH + c], s);
    g_zwpb[c] = s;
    for (int li = 0; li < NLAYERS; li++) {
        const float* wg = Wg + li * COND * WIDTH;
        const float* wb = Wb + li * COND * WIDTH;
        float g = bg[li * WIDTH + c];
        float b = bb[li * WIDTH + c];
        for (int k = 0; k < COND; k++) {
            float zk = z[k];
            g = fmaf(zk, wg[k * WIDTH + c], g);
            b = fmaf(zk, wb[k * WIDTH + c], b);
        }
        g_gamma[li * WIDTH + c] = g;
        g_beta[li * WIDTH + c]  = b;
    }
}

// ============================================================
// Grid build: histogram -> single-block scan -> scatter
// ============================================================
__global__ void hist_kernel(const float* __restrict__ x, int n) {
    int i = blockIdx.x * blockDim.x + threadIdx.x;
    if (i >= n) return;
    const float* bx = g_bx;
    int cx = cell_of(x[i * 3 + 0], bx);
    int cy = cell_of(x[i * 3 + 1], bx);
    int cz = cell_of(x[i * 3 + 2], bx);
    atomicAdd(&g_cnt[(cz * G + cy) * G + cx], 1);
}

__global__ void scan_kernel() {   // 1024 threads, 4 cells each
    __shared__ int sh[1024];
    int t = threadIdx.x;
    int4 v = *reinterpret_cast<const int4*>(&g_cnt[t * 4]);
    int s = v.x + v.y + v.z + v.w;
    sh[t] = s;
    __syncthreads();
    for (int off = 1; off < 1024; off <<= 1) {
        int u = (t >= off) ? sh[t - off] : 0;
        __syncthreads();
        sh[t] += u;
        __syncthreads();
    }
    int ex = sh[t] - s;     // exclusive prefix of this thread's group
    int st0 = ex, st1 = st0 + v.x, st2 = st1 + v.y, st3 = st2 + v.z;
    g_cursor[t * 4 + 0] = st0;  g_cell2[t * 4 + 0] = make_int2(st0, st1);
    g_cursor[t * 4 + 1] = st1;  g_cell2[t * 4 + 1] = make_int2(st1, st2);
    g_cursor[t * 4 + 2] = st2;  g_cell2[t * 4 + 2] = make_int2(st2, st3);
    g_cursor[t * 4 + 3] = st3;  g_cell2[t * 4 + 3] = make_int2(st3, st3 + v.w);
}

__global__ void scatter_kernel(const float* __restrict__ x, int n) {
    int i = blockIdx.x * blockDim.x + threadIdx.x;
    if (i >= n) return;
    const float* bx = g_bx;
    float px = x[i * 3 + 0], py = x[i * 3 + 1], pz = x[i * 3 + 2];
    int cx = cell_of(px, bx), cy = cell_of(py, bx), cz = cell_of(pz, bx);
    int cell = (cz * G + cy) * G + cx;
    int slot = atomicAdd(&g_cursor[cell], 1);
    g_pts[slot] = make_float4(px, py, pz, __int_as_float(i));
}

// ============================================================
// kNN query: quantile grid, expanding Chebyshev rings, exact
// AABB pruning + exact stop rule in x-space.
// ============================================================
__global__ __launch_bounds__(256) void knn_query_kernel(const float* __restrict__ x, int n) {
    __shared__ float bx[G + 1];
    if (threadIdx.x <= G) bx[threadIdx.x] = g_bx[threadIdx.x];
    __syncthreads();

    int s = blockIdx.x * blockDim.x + threadIdx.x;
    if (s >= n) return;
    float4 me = g_pts[s];
    float qx = me.x, qy = me.y, qz = me.z;
    int   qi = __float_as_int(me.w);
    int cx = cell_of(qx, bx), cy = cell_of(qy, bx), cz = cell_of(qz, bx);

    float bd[KNN];
    int   bi[KNN];
#pragma unroll
    for (int r = 0; r < KNN; r++) { bd[r] = 1e30f; bi[r] = -1; }
    float d12 = 1e30f;

    for (int r = 0; r < G; r++) {
        int zlo = max(cz - r, 0), zhi = min(cz + r, G - 1);
        for (int ccz = zlo; ccz <= zhi; ccz++) {
            bool zface = (ccz == cz - r) || (ccz == cz + r);
            float loz = bx[ccz], hiz = bx[ccz + 1];
            float az = fmaxf(fmaxf(loz - qz, qz - hiz), 0.0f);
            int ylo = max(cy - r, 0), yhi = min(cy + r, G - 1);
            for (int ccy = ylo; ccy <= yhi; ccy++) {
                bool face = zface || (ccy == cy - r) || (ccy == cy + r);
                float loy = bx[ccy], hiy = bx[ccy + 1];
                float ay = fmaxf(fmaxf(loy - qy, qy - hiy), 0.0f);
                int step = face ? 1 : (2 * r);
                for (int dx = -r; dx <= r; dx += step) {
                    int ccx = cx + dx;
                    if (ccx < 0 || ccx >= G) continue;
                    float lox = bx[ccx], hix = bx[ccx + 1];
                    float ax = fmaxf(fmaxf(lox - qx, qx - hix), 0.0f);
                    float dmin = fmaf(ax, ax, fmaf(ay, ay, az * az));
                    if (dmin >= d12) continue;
                    int2 se = g_cell2[(ccz * G + ccy) * G + ccx];
                    for (int j = se.x; j < se.y; j++) {
                        float4 p = g_pts[j];
                        float ddx = p.x - qx, ddy = p.y - qy, ddz = p.z - qz;
                        float d = fmaf(ddx, ddx, fmaf(ddy, ddy, ddz * ddz));
                        int pid = __float_as_int(p.w);
                        if (d < d12 && pid != qi) {
                            float cd = d; int ci = pid;
#pragma unroll
                            for (int t = 0; t < KNN; t++) {
                                bool lt = cd < bd[t];
                                float od = bd[t]; int oi = bi[t];
                                bd[t] = lt ? cd : od;  bi[t] = lt ? ci : oi;
                                cd    = lt ? od : cd;  ci    = lt ? oi : ci;
                            }
                            d12 = bd[KNN - 1];
                        }
                    }
                }
            }
        }
        // exact stop: min distance from q to the complement of the searched box
        float f = 1e30f;
        if (cx - r > 0)      f = fminf(f, qx - bx[cx - r]);
        if (cx + r + 1 < G)  f = fminf(f, bx[cx + r + 1] - qx);
        if (cy - r > 0)      f = fminf(f, qy - bx[cy - r]);
        if (cy + r + 1 < G)  f = fminf(f, bx[cy + r + 1] - qy);
        if (cz - r > 0)      f = fminf(f, qz - bx[cz - r]);
        if (cz + r + 1 < G)  f = fminf(f, bx[cz + r + 1] - qz);
        if (f * f >= d12) break;
    }

#pragma unroll
    for (int r = 0; r < KNN; r++)
        g_knn[qi * KNN + r] = bi[r];

    // rel_feat: mean + population std of (x[nbr] - x[q])
    float mx = 0, my = 0, mz = 0;
#pragma unroll
    for (int r = 0; r < KNN; r++) {
        int id = bi[r];
        mx += x[id * 3 + 0] - qx;
        my += x[id * 3 + 1] - qy;
        mz += x[id * 3 + 2] - qz;
    }
    const float inv = 1.0f / (float)KNN;
    mx *= inv; my *= inv; mz *= inv;
    float vx = 0, vy = 0, vz = 0;
#pragma unroll
    for (int r = 0; r < KNN; r++) {
        int id = bi[r];
        float rx = x[id * 3 + 0] - qx - mx;
        float ry = x[id * 3 + 1] - qy - my;
        float rz = x[id * 3 + 2] - qz - mz;
        vx = fmaf(rx, rx, vx); vy = fmaf(ry, ry, vy); vz = fmaf(rz, rz, vz);
    }
    g_rel[qi * 6 + 0] = mx;
    g_rel[qi * 6 + 1] = my;
    g_rel[qi * 6 + 2] = mz;
    g_rel[qi * 6 + 3] = sqrtf(vx * inv);
    g_rel[qi * 6 + 4] = sqrtf(vy * inv);
    g_rel[qi * 6 + 5] = sqrtf(vz * inv);
}

// ============================================================
// Projection: pe = fourier(x) (51 dims), h0 = silu(pe@Wp[0:51] + zwpb)
// ============================================================
__global__ __launch_bounds__(192) void proj_kernel(const float* __restrict__ x,
                                                   const float* __restrict__ B0,
                                                   const float* __restrict__ B1,
                                                   const float* __restrict__ B2,
                                                   const float* __restrict__ Wp,
                                                   float* __restrict__ hout) {
    __shared__ float pe[TPL][52];
    int c    = threadIdx.x;
    int base = blockIdx.x * TPL;

    if (c < TPL) {
        int p = base + c;
        float x0 = x[p * 3 + 0], x1 = x[p * 3 + 1], x2 = x[p * 3 + 2];
        const float* Bs[3] = { B0, B1, B2 };
#pragma unroll
        for (int b = 0; b < 3; b++) {
            const float* B = Bs[b];
#pragma unroll
            for (int j = 0; j < 8; j++) {
                float v = fmaf(x0, B[j], fmaf(x1, B[8 + j], x2 * B[16 + j]));
                float sn, cs;
                sincosf(v, &sn, &cs);
                pe[c][b * 16 + j]     = sn;
                pe[c][b * 16 + 8 + j] = cs;
            }
        }
        pe[c][48] = x0; pe[c][49] = x1; pe[c][50] = x2;
    }
    __syncthreads();

    float acc[TPL];
    float zb = g_zwpb[c];
#pragma unroll
    for (int p = 0; p < TPL; p++) acc[p] = zb;
    for (int k = 0; k < 51; k++) {
        float w = Wp[k * WIDTH + c];
#pragma unroll
        for (int p = 0; p < TPL; p++)
            acc[p] = fmaf(pe[p][k], w, acc[p]);
    }
#pragma unroll
    for (int p = 0; p < TPL; p++) {
        float v = acc[p];
        hout[(base + p) * WIDTH + c] = v / (1.0f + expf(-v));
    }
}

// ============================================================
// Layer: gather+mean agg, mix=[h|agg|rel], 390x192 GEMM with
// packed f32x2 FMA, silu + FiLM. 16 points/block, 192 threads.
// ============================================================
__global__ __launch_bounds__(192) void layer_kernel(const float* __restrict__ hin,
                                                    float* __restrict__ hout,
                                                    const float* __restrict__ Wl,
                                                    const float* __restrict__ bl,
                                                    const float* __restrict__ gamma,
                                                    const float* __restrict__ beta) {
    __shared__ float mix[TPL2 * MIXPAD];     // 16*392*4 = 25088 B
    __shared__ int   nidx[TPL2 * KNN];       // 192
    int c    = threadIdx.x;
    int base = blockIdx.x * TPL2;

    nidx[c] = g_knn[base * KNN + c];         // exactly 192 = 16*12
    __syncthreads();

#pragma unroll
    for (int p = 0; p < TPL2; p++)
        mix[p * MIXPAD + c] = hin[(base + p) * WIDTH + c];
    if (c < 6) {
#pragma unroll
        for (int p = 0; p < TPL2; p++)
            mix[p * MIXPAD + 384 + c] = g_rel[(base + p) * 6 + c];
    }
#pragma unroll 2
    for (int p = 0; p < TPL2; p++) {
        float s = 0.0f;
#pragma unroll
        for (int j = 0; j < KNN; j++)
            s += hin[nidx[p * KNN + j] * WIDTH + c];
        mix[p * MIXPAD + WIDTH + c] = s * (1.0f / (float)KNN);
    }
    __syncthreads();

    ull acc[TPL2];
#pragma unroll
    for (int p = 0; p < TPL2; p++) acc[p] = 0ull;

    for (int k4 = 0; k4 < 97; k4++) {
        int k = k4 * 4;
        float w0 = Wl[(k + 0) * WIDTH + c];
        float w1 = Wl[(k + 1) * WIDTH + c];
        float w2 = Wl[(k + 2) * WIDTH + c];
        float w3 = Wl[(k + 3) * WIDTH + c];
        ull w01 = pk2(w0, w1), w23 = pk2(w2, w3);
#pragma unroll
        for (int p = 0; p < TPL2; p++) {
            ulonglong2 m = *reinterpret_cast<const ulonglong2*>(&mix[p * MIXPAD + k]);
            acc[p] = fma2(m.x, w01, acc[p]);
            acc[p] = fma2(m.y, w23, acc[p]);
        }
    }
    {   // tail k = 388, 389
        ull w01 = pk2(Wl[388 * WIDTH + c], Wl[389 * WIDTH + c]);
#pragma unroll
        for (int p = 0; p < TPL2; p++) {
            ull m = *reinterpret_cast<const ull*>(&mix[p * MIXPAD + 388]);
            acc[p] = fma2(m, w01, acc[p]);
        }
    }

    float bc = bl[c], gc = gamma[c], bt = beta[c];
#pragma unroll
    for (int p = 0; p < TPL2; p++) {
        float a, b;
        upk2(acc[p], a, b);
        float v  = a + b + bc;
        float sv = v / (1.0f + expf(-v));
        hout[(base + p) * WIDTH + c] = fmaf(sv, gc, bt);
    }
}

// ============================================================
// Output: out = (h @ Wout + bout) * 0.01 ; one warp per point
// ============================================================
__global__ __launch_bounds__(256) void out_kernel(const float* __restrict__ h,
                                                  const float* __restrict__ Wout,
                                                  const float* __restrict__ bout,
                                                  float* __restrict__ out, int n) {
    int gwarp = (blockIdx.x * blockDim.x + threadIdx.x) >> 5;
    int lane  = threadIdx.x & 31;
    if (gwarp >= n) return;
    float o0 = 0, o1 = 0, o2 = 0;
    for (int c = lane; c < WIDTH; c += 32) {
        float hv = h[gwarp * WIDTH + c];
        o0 = fmaf(hv, Wout[c * 3 + 0], o0);
        o1 = fmaf(hv, Wout[c * 3 + 1], o1);
        o2 = fmaf(hv, Wout[c * 3 + 2], o2);
    }
#pragma unroll
    for (int off = 16; off; off >>= 1) {
        o0 += __shfl_down_sync(0xffffffffu, o0, off);
        o1 += __shfl_down_sync(0xffffffffu, o1, off);
        o2 += __shfl_down_sync(0xffffffffu, o2, off);
    }
    if (lane == 0) {
        out[gwarp * 3 + 0] = (o0 + bout[0]) * 0.01f;
        out[gwarp * 3 + 1] = (o1 + bout[1]) * 0.01f;
        out[gwarp * 3 + 2] = (o2 + bout[2]) * 0.01f;
    }
}

// ============================================================
extern "C" void kernel_launch(void* const* d_in, const int* in_sizes, int n_in,
                              void* d_out, int out_size) {
    const float* x    = (const float*)d_in[0];
    const float* z    = (const float*)d_in[1];
    const float* B0   = (const float*)d_in[2];
    const float* B1   = (const float*)d_in[3];
    const float* B2   = (const float*)d_in[4];
    const float* Wp   = (const float*)d_in[5];
    const float* bp   = (const float*)d_in[6];
    const float* Wl   = (const float*)d_in[7];
    const float* bl   = (const float*)d_in[8];
    const float* Wg   = (const float*)d_in[9];
    const float* bg   = (const float*)d_in[10];
    const float* Wb   = (const float*)d_in[11];
    const float* Wbb  = (const float*)d_in[12];
    const float* Wout = (const float*)d_in[13];
    const float* bout = (const float*)d_in[14];
    float* out = (float*)d_out;

    int n = in_sizes[0] / 3;   // 32768

    float *h0, *h1;
    cudaGetSymbolAddress((void**)&h0, g_h0);
    cudaGetSymbolAddress((void**)&h1, g_h1);
    float *gma, *bta;
    cudaGetSymbolAddress((void**)&gma, g_gamma);
    cudaGetSymbolAddress((void**)&bta, g_beta);
    void* cntp;
    cudaGetSymbolAddress(&cntp, g_cnt);

    setup_kernel<<<1, WIDTH>>>(z, Wp, bp, Wg, bg, Wb, Wbb);

    // ---- grid kNN pipeline ----
    cudaMemsetAsync(cntp, 0, NCELLS * sizeof(int));
    hist_kernel<<<n / 256, 256>>>(x, n);
    scan_kernel<<<1, 1024>>>();
    scatter_kernel<<<n / 256, 256>>>(x, n);
    knn_query_kernel<<<n / 256, 256>>>(x, n);

    proj_kernel<<<n / TPL, WIDTH>>>(x, B0, B1, B2, Wp, h0);

    float* bufs[2] = { h0, h1 };
    for (int li = 0; li < NLAYERS; li++) {
        const float* hin = bufs[li & 1];
        float*       ho  = bufs[(li + 1) & 1];
        layer_kernel<<<n / TPL2, 192>>>(hin, ho,
            Wl + (size_t)li * MIXDIM * WIDTH, bl + li * WIDTH,
            gma + li * WIDTH, bta + li * WIDTH);
    }
    const float* hfin = bufs[NLAYERS & 1];

    out_kernel<<<(n * 32 + 255) / 256, 256>>>(hfin, Wout, bout, out, n);
}